// round 1
// baseline (speedup 1.0000x reference)
#include <cuda_runtime.h>
#include <cstdint>

// ============================================================================
// Problem: out[b,s,e] = sum_{h,d} heads[b,s,h,d] * W_out[h*64+d, e] + b_out[e]
//   heads[b,s,h,d] = sum_w cos(x[b,s,w] + theta[h,w]) * W_proj[h,w,d] + b_proj[h,d]
// Algebraic collapse (cos(a+b) = cos a cos b - sin a sin b, all downstream linear):
//   out[b,s,e] = sum_{w<8} cos(x_w)*Wc[w,e] + sin(x_w)*Wc[8+w,e] + beff[e]
// Wc is a fixed 16x768 matrix precomputed per launch from theta/W_proj/W_out.
// ============================================================================

#define H_    12
#define NW_   8
#define DK_   64
#define E_    768
#define NTOK  32768        // B*S = 8*4096
#define TOK_PER_BLK 64
#define MAIN_THREADS 384   // each thread owns 2 output columns

// Scratch (device globals: no allocation allowed in kernel_launch)
__device__ float g_scratch[H_ * 17 * E_];   // per-head partials: 16 Wc rows + 1 bias row
__device__ float g_Wc[16 * E_];             // collapsed 16x768 matrix
__device__ float g_beff[E_];                // collapsed bias

// ---------------------------------------------------------------------------
// Packed fp32x2 FMA (sm_100+): d = a*b + c on two fp32 lanes in one instr.
// ---------------------------------------------------------------------------
__device__ __forceinline__ unsigned long long fma2(unsigned long long a,
                                                   unsigned long long b,
                                                   unsigned long long c) {
    unsigned long long d;
    asm("fma.rn.f32x2 %0, %1, %2, %3;" : "=l"(d) : "l"(a), "l"(b), "l"(c));
    return d;
}

// ---------------------------------------------------------------------------
// Kernel A: per-(h, e-chunk) partial reduction over d.
// grid = (6, 12), block = 128. Each thread owns one output column e for one h.
// ---------------------------------------------------------------------------
__global__ void qmha_precompute_partial(const float* __restrict__ theta,
                                        const float* __restrict__ W_proj,
                                        const float* __restrict__ b_proj,
                                        const float* __restrict__ W_out) {
    const int h = blockIdx.y;
    const int e = blockIdx.x * 128 + threadIdx.x;

    __shared__ float pc[NW_][DK_];   // cos(theta_hw) * W_proj[h,w,d]
    __shared__ float ps[NW_][DK_];   // -sin(theta_hw) * W_proj[h,w,d]
    __shared__ float bp[DK_];

    for (int idx = threadIdx.x; idx < NW_ * DK_; idx += 128) {
        int w = idx >> 6, d = idx & 63;
        float s, c;
        sincosf(theta[h * NW_ + w], &s, &c);
        float p = W_proj[(h * NW_ + w) * DK_ + d];
        pc[w][d] = c * p;
        ps[w][d] = -s * p;
    }
    if (threadIdx.x < DK_) bp[threadIdx.x] = b_proj[h * DK_ + threadIdx.x];
    __syncthreads();

    float accc[NW_] = {0.f}, accs[NW_] = {0.f};
    float accb = 0.f;
    #pragma unroll 4
    for (int d = 0; d < DK_; d++) {
        float wo = W_out[(h * DK_ + d) * E_ + e];
        #pragma unroll
        for (int w = 0; w < NW_; w++) {
            accc[w] = fmaf(pc[w][d], wo, accc[w]);
            accs[w] = fmaf(ps[w][d], wo, accs[w]);
        }
        accb = fmaf(bp[d], wo, accb);
    }
    #pragma unroll
    for (int w = 0; w < NW_; w++) {
        g_scratch[(h * 17 + w) * E_ + e] = accc[w];
        g_scratch[(h * 17 + 8 + w) * E_ + e] = accs[w];
    }
    g_scratch[(h * 17 + 16) * E_ + e] = accb;
}

// ---------------------------------------------------------------------------
// Kernel B: reduce partials over h into g_Wc / g_beff.
// grid = 3, block = 256.
// ---------------------------------------------------------------------------
__global__ void qmha_reduce(const float* __restrict__ b_out) {
    const int e = blockIdx.x * 256 + threadIdx.x;
    #pragma unroll
    for (int k = 0; k < 16; k++) {
        float s = 0.f;
        #pragma unroll
        for (int h = 0; h < H_; h++) s += g_scratch[(h * 17 + k) * E_ + e];
        g_Wc[k * E_ + e] = s;
    }
    float s = b_out[e];
    #pragma unroll
    for (int h = 0; h < H_; h++) s += g_scratch[(h * 17 + 16) * E_ + e];
    g_beff[e] = s;
}

// ---------------------------------------------------------------------------
// Main kernel: per token, out[:, e] = sum_j cs[j] * Wc[j, e] + beff[e].
// Each thread owns 2 consecutive output columns -> all math in packed f32x2.
// cos/sin values staged in shared PRE-DUPLICATED as {v, v} float2 so the
// multiplier loads directly as a packed 64-bit operand (no pack movs).
// grid = 512, block = 384.
// ---------------------------------------------------------------------------
__global__ void __launch_bounds__(MAIN_THREADS, 2)
qmha_main(const float* __restrict__ x, float* __restrict__ out) {
    __shared__ __align__(16) float2 cs[TOK_PER_BLK * 16];

    const int p = threadIdx.x;                   // column-pair index 0..383
    const int tok0 = blockIdx.x * TOK_PER_BLK;

    // Load this thread's 16x2 slice of Wc + bias as packed 64-bit values.
    unsigned long long W2[16];
    #pragma unroll
    for (int j = 0; j < 16; j++)
        W2[j] = reinterpret_cast<const unsigned long long*>(g_Wc)[j * MAIN_THREADS + p];
    const unsigned long long bias2 =
        reinterpret_cast<const unsigned long long*>(g_beff)[p];

    // Stage cos/sin for this block's 64 tokens (8 wires each).
    for (int idx = p; idx < TOK_PER_BLK * NW_; idx += MAIN_THREADS) {
        int t = idx >> 3, w = idx & 7;
        float xv = x[(tok0 + t) * E_ + w];
        float s, c;
        __sincosf(xv, &s, &c);
        cs[t * 16 + w]     = make_float2(c, c);
        cs[t * 16 + 8 + w] = make_float2(s, s);
    }
    __syncthreads();

    unsigned long long* outp =
        reinterpret_cast<unsigned long long*>(out) + (size_t)tok0 * MAIN_THREADS + p;
    const unsigned cs_base = (unsigned)__cvta_generic_to_shared(cs);

    #pragma unroll 2
    for (int t = 0; t < TOK_PER_BLK; t++) {
        const unsigned addr = cs_base + t * 128;   // 16 entries * 8B
        unsigned long long c[16];
        #pragma unroll
        for (int j = 0; j < 16; j += 2)
            asm("ld.shared.v2.b64 {%0,%1}, [%2];"
                : "=l"(c[j]), "=l"(c[j + 1]) : "r"(addr + j * 8));
        unsigned long long acc = bias2;
        #pragma unroll
        for (int j = 0; j < 16; j++) acc = fma2(c[j], W2[j], acc);
        outp[(size_t)t * MAIN_THREADS] = acc;
    }
}

// ---------------------------------------------------------------------------
extern "C" void kernel_launch(void* const* d_in, const int* in_sizes, int n_in,
                              void* d_out, int out_size) {
    const float* x      = (const float*)d_in[0];   // [8,4096,768]
    const float* theta  = (const float*)d_in[1];   // [12,8]
    const float* W_proj = (const float*)d_in[2];   // [12,8,64]
    const float* b_proj = (const float*)d_in[3];   // [12,64]
    const float* W_out  = (const float*)d_in[4];   // [768,768]
    const float* b_out  = (const float*)d_in[5];   // [768]
    float* out = (float*)d_out;

    qmha_precompute_partial<<<dim3(6, 12), 128>>>(theta, W_proj, b_proj, W_out);
    qmha_reduce<<<3, 256>>>(b_out);
    qmha_main<<<NTOK / TOK_PER_BLK, MAIN_THREADS>>>(x, out);
}

// round 2
// speedup vs baseline: 1.3478x; 1.3478x over previous
#include <cuda_runtime.h>
#include <cstdint>

// ============================================================================
// out[b,s,e] = sum_{w<8} cos(x_w)*Wc[w,e] + sin(x_w)*Wc[8+w,e] + beff[e]
// Wc (16x768) precomputed from theta/W_proj/W_out via:
//   Wc[w,e]   =  cos(theta_hw) * sum_d W_proj[h,w,d] * W_out[h*64+d, e]  (summed h)
//   Wc[8+w,e] = -sin(theta_hw) * (same inner sum)
//   beff[e]   =  b_out[e] + sum_{h,d} b_proj[h,d] * W_out[h*64+d, e]
// ============================================================================

#define H_    12
#define NW_   8
#define DK_   64
#define E_    768
#define NTOK  32768
#define TOK_PER_BLK 64
#define MAIN_THREADS 384
#define NPART 24            // r-chunks of 32 rows (2 chunks per head)

__device__ float g_scratch[NPART * 17 * E_];   // 17 rows (16 Wc + bias) per partial
__device__ float g_Wc[16 * E_];
__device__ float g_beff[E_];

__device__ __forceinline__ unsigned long long fma2(unsigned long long a,
                                                   unsigned long long b,
                                                   unsigned long long c) {
    unsigned long long d;
    asm("fma.rn.f32x2 %0, %1, %2, %3;" : "=l"(d) : "l"(a), "l"(b), "l"(c));
    return d;
}

// ---------------------------------------------------------------------------
// Kernel P: grid (6 e-chunks, 24 r-chunks), block 128.
// Each block: 128 e-cols x 32 r-rows (within one head). Trig factored out of
// the d-loop; 32 fully-unrolled coalesced W_out loads per thread (MLP=32).
// ---------------------------------------------------------------------------
__global__ void qmha_pre(const float* __restrict__ theta,
                         const float* __restrict__ W_proj,
                         const float* __restrict__ b_proj,
                         const float* __restrict__ W_out) {
    const int tid = threadIdx.x;
    const int e = blockIdx.x * 128 + tid;
    const int rc = blockIdx.y;          // 0..23
    const int h = rc >> 1;
    const int d0 = (rc & 1) * 32;

    __shared__ float Wp[NW_][32];
    __shared__ float trigc[NW_], trigs[NW_];
    __shared__ float bp[32];

    #pragma unroll
    for (int i = tid; i < NW_ * 32; i += 128) {
        int w = i >> 5, dd = i & 31;
        Wp[w][dd] = W_proj[(h * NW_ + w) * DK_ + d0 + dd];
    }
    if (tid < NW_) {
        float s, c;
        sincosf(theta[h * NW_ + tid], &s, &c);
        trigc[tid] = c;
        trigs[tid] = -s;
    }
    if (tid < 32) bp[tid] = b_proj[h * DK_ + d0 + tid];
    __syncthreads();

    float acc[NW_] = {0.f, 0.f, 0.f, 0.f, 0.f, 0.f, 0.f, 0.f};
    float accb = 0.f;
    #pragma unroll
    for (int dd = 0; dd < 32; dd++) {
        float wo = W_out[(h * DK_ + d0 + dd) * E_ + e];
        accb = fmaf(bp[dd], wo, accb);
        #pragma unroll
        for (int w = 0; w < NW_; w++) acc[w] = fmaf(Wp[w][dd], wo, acc[w]);
    }

    float* sc = g_scratch + rc * 17 * E_;
    #pragma unroll
    for (int w = 0; w < NW_; w++) {
        sc[w * E_ + e]        = trigc[w] * acc[w];
        sc[(8 + w) * E_ + e]  = trigs[w] * acc[w];
    }
    sc[16 * E_ + e] = accb;
}

// ---------------------------------------------------------------------------
// Kernel R: reduce 24 partials. grid 17 (one per output row), block 768.
// ---------------------------------------------------------------------------
__global__ void qmha_reduce(const float* __restrict__ b_out) {
    const int k = blockIdx.x;           // 0..16
    const int e = threadIdx.x;
    float s = 0.f;
    #pragma unroll
    for (int p = 0; p < NPART; p++) s += g_scratch[(p * 17 + k) * E_ + e];
    if (k == 16) g_beff[e] = s + b_out[e];
    else         g_Wc[k * E_ + e] = s;
}

// ---------------------------------------------------------------------------
// Main kernel: per token, out[:, e] = sum_j cs[j] * Wc[j, e] + beff[e].
// Thread owns 2 consecutive cols; all math packed f32x2; cs staged in shared
// pre-duplicated {v,v} so ld.shared.v2.b64 feeds fma2 directly (broadcast).
// ---------------------------------------------------------------------------
__global__ void __launch_bounds__(MAIN_THREADS, 2)
qmha_main(const float* __restrict__ x, float* __restrict__ out) {
    __shared__ __align__(16) float2 cs[TOK_PER_BLK * 16];

    const int p = threadIdx.x;
    const int tok0 = blockIdx.x * TOK_PER_BLK;

    unsigned long long W2[16];
    #pragma unroll
    for (int j = 0; j < 16; j++)
        W2[j] = reinterpret_cast<const unsigned long long*>(g_Wc)[j * MAIN_THREADS + p];
    const unsigned long long bias2 =
        reinterpret_cast<const unsigned long long*>(g_beff)[p];

    for (int idx = p; idx < TOK_PER_BLK * NW_; idx += MAIN_THREADS) {
        int t = idx >> 3, w = idx & 7;
        float xv = x[(size_t)(tok0 + t) * E_ + w];
        float s, c;
        __sincosf(xv, &s, &c);
        cs[t * 16 + w]     = make_float2(c, c);
        cs[t * 16 + 8 + w] = make_float2(s, s);
    }
    __syncthreads();

    unsigned long long* outp =
        reinterpret_cast<unsigned long long*>(out) + (size_t)tok0 * MAIN_THREADS + p;
    const unsigned cs_base = (unsigned)__cvta_generic_to_shared(cs);

    #pragma unroll 2
    for (int t = 0; t < TOK_PER_BLK; t++) {
        const unsigned addr = cs_base + t * 128;
        unsigned long long c[16];
        #pragma unroll
        for (int j = 0; j < 16; j += 2)
            asm("ld.shared.v2.b64 {%0,%1}, [%2];"
                : "=l"(c[j]), "=l"(c[j + 1]) : "r"(addr + j * 8));
        unsigned long long acc = bias2;
        #pragma unroll
        for (int j = 0; j < 16; j++) acc = fma2(c[j], W2[j], acc);
        outp[(size_t)t * MAIN_THREADS] = acc;
    }
}

// ---------------------------------------------------------------------------
extern "C" void kernel_launch(void* const* d_in, const int* in_sizes, int n_in,
                              void* d_out, int out_size) {
    const float* x      = (const float*)d_in[0];
    const float* theta  = (const float*)d_in[1];
    const float* W_proj = (const float*)d_in[2];
    const float* b_proj = (const float*)d_in[3];
    const float* W_out  = (const float*)d_in[4];
    const float* b_out  = (const float*)d_in[5];
    float* out = (float*)d_out;

    qmha_pre<<<dim3(6, NPART), 128>>>(theta, W_proj, b_proj, W_out);
    qmha_reduce<<<17, E_>>>(b_out);
    qmha_main<<<NTOK / TOK_PER_BLK, MAIN_THREADS>>>(x, out);
}